// round 9
// baseline (speedup 1.0000x reference)
#include <cuda_runtime.h>
#include <cstddef>
#include <cstdint>

#define ALPHA  0.2f
#define LOG2E  1.4426950408889634f

#define NN 8
#define HH 64
#define WD 64
#define TT 8
#define VV 32
#define OO 16

// inter-kernel scratch: att_sum[pair][w][v]
__device__ float g_asum[NN * HH * WD * VV];   // 4 MB

// ---------------- helpers ----------------
__device__ __forceinline__ float ex2f(float x) {
    float y; asm("ex2.approx.f32 %0, %1;" : "=f"(y) : "f"(x)); return y;
}
__device__ __forceinline__ float rcpf(float x) {
    float y; asm("rcp.approx.f32 %0, %1;" : "=f"(y) : "f"(x)); return y;
}
__device__ __forceinline__ float2 ffma2(float2 a, float2 b, float2 c) {
    unsigned long long A, B, C, D;
    A = *reinterpret_cast<unsigned long long*>(&a);
    B = *reinterpret_cast<unsigned long long*>(&b);
    C = *reinterpret_cast<unsigned long long*>(&c);
    asm("fma.rn.f32x2 %0, %1, %2, %3;" : "=l"(D) : "l"(A), "l"(B), "l"(C));
    return *reinterpret_cast<float2*>(&D);
}
__device__ __forceinline__ float2 fmul2(float2 a, float2 b) {
    unsigned long long A, B, D;
    A = *reinterpret_cast<unsigned long long*>(&a);
    B = *reinterpret_cast<unsigned long long*>(&b);
    asm("mul.rn.f32x2 %0, %1, %2;" : "=l"(D) : "l"(A), "l"(B));
    return *reinterpret_cast<float2*>(&D);
}

// ============================================================================
// Kernel A: attention sums.  grid = 1024: pair = bid>>1 (n*64+hh), half = bid&1
// Each CTA: full E tables, pass A/B for i in [half*16, half*16+16).
// exp factorization: exp(leaky(x1+x2)) = max(2^x1*2^x2, 2^(.2x1)*2^(.2x2))
// ============================================================================

#define E2_STRIDE 66   // 2-way-conflict scalar reads, float2-aligned pair reads
#define RA_STRIDE 18   // r rows [j][i-local], 2-way store conflict

struct SmemA {
    float2 E1pk[WD * VV];          // 16384 B  [w][i] = (2^e1, 2^(.2 e1))
    float  E2p[VV * E2_STRIDE];    //  8448 B  [j][w]
    float  E2n[VV * E2_STRIDE];    //  8448 B  [j][w]
    float  r[VV * RA_STRIDE];      //  2304 B  [j][i-local]
    float2 wav[TT];                //    64 B  (wa1[t], wa2[t])
};                                  // 35,648 B -> 6 CTAs/SM

__global__ __launch_bounds__(256, 6)
void gat_attn_kernel(const float* __restrict__ hin,
                     const float* __restrict__ W,
                     const float* __restrict__ a) {
    extern __shared__ char smem_raw[];
    SmemA& S = *reinterpret_cast<SmemA*>(smem_raw);
    const int tid  = threadIdx.x;
    const int lane = tid & 31;
    const int warp = tid >> 5;
    const int pair = blockIdx.x >> 1;         // n*64 + hh
    const int half = blockIdx.x & 1;
    const float* __restrict__ hbase = hin + (size_t)pair * (WD * TT * VV);

    if (tid < TT) {
        float w1 = 0.f, w2 = 0.f;
        #pragma unroll
        for (int o = 0; o < OO; o++) {
            float wv = W[tid * OO + o];
            w1 += wv * a[o];
            w2 += wv * a[OO + o];
        }
        S.wav[tid] = make_float2(w1 * LOG2E, w2 * LOG2E);
    }
    __syncthreads();

    // ---- phase 1: logits -> exponential tables (both halves compute all) ----
    {
        #pragma unroll
        for (int s = 0; s < 2; s++) {
            const int slot = tid + s * 256;
            const int w  = slot >> 3;
            const int vq = slot & 7;
            float4 s1 = make_float4(0.f, 0.f, 0.f, 0.f);
            float4 s2 = make_float4(0.f, 0.f, 0.f, 0.f);
            #pragma unroll
            for (int t = 0; t < TT; t++) {
                const float2 wa = S.wav[t];                    // broadcast LDS.64
                const float4 h4 = *reinterpret_cast<const float4*>(
                    &hbase[(w * TT + t) * VV + 4 * vq]);       // coalesced LDG.128
                s1.x = fmaf(h4.x, wa.x, s1.x);  s2.x = fmaf(h4.x, wa.y, s2.x);
                s1.y = fmaf(h4.y, wa.x, s1.y);  s2.y = fmaf(h4.y, wa.y, s2.y);
                s1.z = fmaf(h4.z, wa.x, s1.z);  s2.z = fmaf(h4.z, wa.y, s2.z);
                s1.w = fmaf(h4.w, wa.x, s1.w);  s2.w = fmaf(h4.w, wa.y, s2.w);
            }
            const float l1[4] = {s1.x, s1.y, s1.z, s1.w};
            const float l2[4] = {s2.x, s2.y, s2.z, s2.w};
            #pragma unroll
            for (int c = 0; c < 4; c++) {
                const int v = 4 * vq + c;
                S.E1pk[w * VV + v] = make_float2(ex2f(l1[c]), ex2f(ALPHA * l1[c]));
                S.E2p[v * E2_STRIDE + w] = ex2f(l2[c]);
                S.E2n[v * E2_STRIDE + w] = ex2f(ALPHA * l2[c]);
            }
        }
    }
    __syncthreads();

    const int i0g = half * 16 + warp * 2;     // this warp's 2 global i rows
    const int il0 = warp * 2;                 // local index within half

    // ---- pass A: r[j][il] = 1 / sum_w max(E1p*E2p, E1n*E2n) ----
    {
        const int j = lane;
        float s0 = 0.f, s1 = 0.f;
        #pragma unroll 4
        for (int w = 0; w < WD; w++) {
            const float e2p = S.E2p[j * E2_STRIDE + w];
            const float e2n = S.E2n[j * E2_STRIDE + w];
            const float4 A = *reinterpret_cast<const float4*>(&S.E1pk[w * VV + i0g]);
            s0 += fmaxf(A.x * e2p, A.y * e2n);
            s1 += fmaxf(A.z * e2p, A.w * e2n);
        }
        *reinterpret_cast<float2*>(&S.r[j * RA_STRIDE + il0]) =
            make_float2(rcpf(s0), rcpf(s1));
    }
    __syncthreads();

    // ---- pass B: asum[w][i] = sum_j max(...) * r[j][i]; write to g_asum ----
    {
        const int w0 = 2 * lane;
        float2 E1p2[2], E1n2[2];
        #pragma unroll
        for (int k = 0; k < 2; k++) {
            const float2 ea = S.E1pk[w0 * VV + i0g + k];
            const float2 eb = S.E1pk[(w0 + 1) * VV + i0g + k];
            E1p2[k] = make_float2(ea.x, eb.x);
            E1n2[k] = make_float2(ea.y, eb.y);
        }
        float2 acc[2];
        acc[0] = make_float2(0.f, 0.f);
        acc[1] = make_float2(0.f, 0.f);

        #pragma unroll 4
        for (int j = 0; j < VV; j++) {
            const float2 p2 = *reinterpret_cast<const float2*>(&S.E2p[j * E2_STRIDE + w0]);
            const float2 n2 = *reinterpret_cast<const float2*>(&S.E2n[j * E2_STRIDE + w0]);
            const float2 rr = *reinterpret_cast<const float2*>(&S.r[j * RA_STRIDE + il0]);
            const float rk[2] = {rr.x, rr.y};
            #pragma unroll
            for (int k = 0; k < 2; k++) {
                const float2 pp = fmul2(E1p2[k], p2);
                const float2 pn = fmul2(E1n2[k], n2);
                acc[k].x = fmaf(fmaxf(pp.x, pn.x), rk[k], acc[k].x);
                acc[k].y = fmaf(fmaxf(pp.y, pn.y), rk[k], acc[k].y);
            }
        }
        float* dst = g_asum + (size_t)pair * (WD * VV);
        *reinterpret_cast<float2*>(&dst[w0 * VV + i0g]) =
            make_float2(acc[0].x, acc[1].x);
        *reinterpret_cast<float2*>(&dst[(w0 + 1) * VV + i0g]) =
            make_float2(acc[0].y, acc[1].y);
    }
}

// ============================================================================
// Kernel B: output.  grid = 1024: pair = bid>>1, whalf = (bid&1)*32.
// Each CTA: inline adjn prep, asum slice, warp owns 4 w's.
// ============================================================================

struct SmemB {
    float  hg[8 * TT * VV];        //  8192 B  per-warp 1 KB h*g slab
    float  adjn[VV * VV];          //  4096 B  [v][u]
    float  asum[32 * VV];          //  4096 B  [w-local][v]
    float4 Wt4[OO * 2];            //   512 B  [o][half]: W[4h..4h+3][o]
    float  scr[64];                //   256 B  reduction scratch
};                                  // 17,152 B

__global__ __launch_bounds__(256, 5)
void gat_out_kernel(const float* __restrict__ hin,
                    const float* __restrict__ W,
                    const float* __restrict__ Bp,
                    float* __restrict__ out) {
    extern __shared__ char smem_raw[];
    SmemB& S = *reinterpret_cast<SmemB*>(smem_raw);
    const int tid  = threadIdx.x;
    const int lane = tid & 31;
    const int warp = tid >> 5;
    const int pair  = blockIdx.x >> 1;        // n*64 + hh
    const int whalf = (blockIdx.x & 1) * 32;
    const int n  = pair >> 6;
    const int hh = pair & 63;
    const float* __restrict__ hbase = hin + (size_t)pair * (WD * TT * VV);

    // ---- inline prep: adjn + Wt4 ----
    {
        float v[4]; float mn = 1e30f, mx = -1e30f;
        #pragma unroll
        for (int k = 0; k < 4; k++) {
            const int e = tid + k * 256;
            float x = Bp[e] + ((e >> 5) == (e & 31) ? 1.0f : 0.0f);
            v[k] = x;
            mn = fminf(mn, x); mx = fmaxf(mx, x);
        }
        #pragma unroll
        for (int o = 16; o; o >>= 1) {
            mn = fminf(mn, __shfl_xor_sync(0xFFFFFFFFu, mn, o));
            mx = fmaxf(mx, __shfl_xor_sync(0xFFFFFFFFu, mx, o));
        }
        if (lane == 0) { S.scr[warp] = mn; S.scr[8 + warp] = mx; }
        __syncthreads();
        if (tid == 0) {
            float m1 = S.scr[0], m2 = S.scr[8];
            #pragma unroll
            for (int q = 1; q < 8; q++) {
                m1 = fminf(m1, S.scr[q]); m2 = fmaxf(m2, S.scr[8 + q]);
            }
            S.scr[16] = m1; S.scr[17] = m2;
        }
        if (tid < 32) {
            const int o = tid >> 1, hf = tid & 1;
            S.Wt4[o * 2 + hf] = make_float4(W[(4 * hf + 0) * OO + o],
                                            W[(4 * hf + 1) * OO + o],
                                            W[(4 * hf + 2) * OO + o],
                                            W[(4 * hf + 3) * OO + o]);
        }
        __syncthreads();
        const float gmn = S.scr[16];
        const float inv = 1.0f / (S.scr[17] - gmn);
        #pragma unroll
        for (int k = 0; k < 4; k++) {
            const int e = tid + k * 256;
            S.adjn[e] = (v[k] - gmn) * inv;
        }
        __syncthreads();
        if (tid < 32) {
            float s = 0.f;
            #pragma unroll
            for (int q = 0; q < 8; q++) {
                const float4 t4 = *reinterpret_cast<const float4*>(&S.adjn[tid * VV + 4 * q]);
                s += t4.x + t4.y + t4.z + t4.w;
            }
            S.scr[32 + tid] = rsqrtf(s);
        }
        __syncthreads();
        #pragma unroll
        for (int k = 0; k < 4; k++) {
            const int e = tid + k * 256;
            S.adjn[e] = S.adjn[e] * S.scr[32 + (e >> 5)] * S.scr[32 + (e & 31)];
        }
    }
    // ---- load asum slice (32 w's = 1024 floats) ----
    {
        const float* src = g_asum + (size_t)pair * (WD * VV) + whalf * VV;
        reinterpret_cast<float4*>(S.asum)[tid] =
            reinterpret_cast<const float4*>(src)[tid];
    }
    __syncthreads();

    // ---- phase 3 (warp-autonomous): warp owns w-local = warp*4 .. +3 ----
    {
        const int u = lane;
        float* hgw = S.hg + warp * (TT * VV);
        const int sA = lane, sB = lane + 32;
        const int tA = sA >> 3, qA = sA & 7;
        const int tB = sB >> 3, qB = sB & 7;
        const int wl0 = warp * 4;

        // prefetch first w
        float4 ha = *reinterpret_cast<const float4*>(
            &hbase[((whalf + wl0) * TT + tA) * VV + 4 * qA]);
        float4 hb = *reinterpret_cast<const float4*>(
            &hbase[((whalf + wl0) * TT + tB) * VV + 4 * qB]);

        #pragma unroll 1
        for (int c = 0; c < 4; c++) {
            const int wl = wl0 + c;                 // local 0..31
            const int wg = whalf + wl;              // global w
            // stage hg = h * asum
            {
                const float4 a1 = *reinterpret_cast<const float4*>(&S.asum[wl * VV + 4 * qA]);
                const float4 a2 = *reinterpret_cast<const float4*>(&S.asum[wl * VV + 4 * qB]);
                float2 g1 = fmul2(make_float2(ha.x, ha.y), make_float2(a1.x, a1.y));
                float2 g2 = fmul2(make_float2(ha.z, ha.w), make_float2(a1.z, a1.w));
                *reinterpret_cast<float4*>(&hgw[tA * VV + 4 * qA]) =
                    make_float4(g1.x, g1.y, g2.x, g2.y);
                g1 = fmul2(make_float2(hb.x, hb.y), make_float2(a2.x, a2.y));
                g2 = fmul2(make_float2(hb.z, hb.w), make_float2(a2.z, a2.w));
                *reinterpret_cast<float4*>(&hgw[tB * VV + 4 * qB]) =
                    make_float4(g1.x, g1.y, g2.x, g2.y);
            }
            __syncwarp();
            if (c < 3) {   // prefetch next w, hidden behind compute
                ha = *reinterpret_cast<const float4*>(
                    &hbase[((wg + 1) * TT + tA) * VV + 4 * qA]);
                hb = *reinterpret_cast<const float4*>(
                    &hbase[((wg + 1) * TT + tB) * VV + 4 * qB]);
            }

            // v-contraction: P[t][u] = sum_v hg[t][v] * adjn[v][u]
            float2 acc2[TT];
            #pragma unroll
            for (int t = 0; t < TT; t++) acc2[t] = make_float2(0.f, 0.f);
            #pragma unroll
            for (int vq = 0; vq < 8; vq++) {
                const float2 adjA = make_float2(S.adjn[(4 * vq + 0) * VV + u],
                                                S.adjn[(4 * vq + 1) * VV + u]);
                const float2 adjB = make_float2(S.adjn[(4 * vq + 2) * VV + u],
                                                S.adjn[(4 * vq + 3) * VV + u]);
                #pragma unroll
                for (int t = 0; t < TT; t++) {
                    const float4 h4 = *reinterpret_cast<const float4*>(&hgw[t * VV + 4 * vq]);
                    acc2[t] = ffma2(make_float2(h4.x, h4.y), adjA, acc2[t]);
                    acc2[t] = ffma2(make_float2(h4.z, h4.w), adjB, acc2[t]);
                }
            }
            float2 Pt2[4];
            #pragma unroll
            for (int tp = 0; tp < 4; tp++)
                Pt2[tp] = make_float2(acc2[2 * tp].x + acc2[2 * tp].y,
                                      acc2[2 * tp + 1].x + acc2[2 * tp + 1].y);

            // o-loop
            float* outp = out + ((size_t)((n * WD + wg) * HH + hh)) * (OO * VV) + u;
            #pragma unroll
            for (int o = 0; o < OO; o++) {
                const float4 Wa = S.Wt4[2 * o];
                const float4 Wb = S.Wt4[2 * o + 1];
                float2 s2 = make_float2(0.f, 0.f);
                s2 = ffma2(Pt2[0], make_float2(Wa.x, Wa.y), s2);
                s2 = ffma2(Pt2[1], make_float2(Wa.z, Wa.w), s2);
                s2 = ffma2(Pt2[2], make_float2(Wb.x, Wb.y), s2);
                s2 = ffma2(Pt2[3], make_float2(Wb.z, Wb.w), s2);
                const float s = s2.x + s2.y;
                float r;
                if (s >= 0.0f)            r = s;
                else if (s > -0.0625f)    r = s * fmaf(s, fmaf(s, 0.166666667f, 0.5f), 1.0f);
                else                      r = ex2f(s * LOG2E) - 1.0f;
                outp[o * VV] = r;
            }
            __syncwarp();   // protect hgw before next iteration's stores
        }
    }
}

// ---------------- launch ----------------
extern "C" void kernel_launch(void* const* d_in, const int* in_sizes, int n_in,
                              void* d_out, int out_size) {
    const float *h = nullptr, *W = nullptr, *a = nullptr, *Bp = nullptr;
    for (int i = 0; i < n_in; i++) {
        switch (in_sizes[i]) {
            case NN * HH * WD * TT * VV: h  = (const float*)d_in[i]; break; // 8388608
            case TT * OO:                W  = (const float*)d_in[i]; break; // 128
            case 2 * OO:                 a  = (const float*)d_in[i]; break; // 32
            case VV * VV:                Bp = (const float*)d_in[i]; break; // 1024
            default: break;
        }
    }
    float* out = (float*)d_out;

    cudaFuncSetAttribute(gat_attn_kernel,
                         cudaFuncAttributeMaxDynamicSharedMemorySize,
                         (int)sizeof(SmemA));
    cudaFuncSetAttribute(gat_out_kernel,
                         cudaFuncAttributeMaxDynamicSharedMemorySize,
                         (int)sizeof(SmemB));

    gat_attn_kernel<<<NN * HH * 2, 256, sizeof(SmemA)>>>(h, W, a);
    gat_out_kernel<<<NN * HH * 2, 256, sizeof(SmemB)>>>(h, W, Bp, out);
}

// round 10
// speedup vs baseline: 1.1908x; 1.1908x over previous
#include <cuda_runtime.h>
#include <cstddef>
#include <cstdint>

#define ALPHA  0.2f
#define LOG2E  1.4426950408889634f

// Problem dims (fixed by the reference)
#define NN 8
#define HH 64
#define WD 64
#define TT 8
#define VV 32
#define OO 16

// ---------------- helpers ----------------
__device__ __forceinline__ float ex2f(float x) {
    float y; asm("ex2.approx.f32 %0, %1;" : "=f"(y) : "f"(x)); return y;
}
__device__ __forceinline__ float rcpf(float x) {
    float y; asm("rcp.approx.f32 %0, %1;" : "=f"(y) : "f"(x)); return y;
}
__device__ __forceinline__ float2 ffma2(float2 a, float2 b, float2 c) {
    unsigned long long A, B, C, D;
    A = *reinterpret_cast<unsigned long long*>(&a);
    B = *reinterpret_cast<unsigned long long*>(&b);
    C = *reinterpret_cast<unsigned long long*>(&c);
    asm("fma.rn.f32x2 %0, %1, %2, %3;" : "=l"(D) : "l"(A), "l"(B), "l"(C));
    return *reinterpret_cast<float2*>(&D);
}
__device__ __forceinline__ float2 fmul2(float2 a, float2 b) {
    unsigned long long A, B, D;
    A = *reinterpret_cast<unsigned long long*>(&a);
    B = *reinterpret_cast<unsigned long long*>(&b);
    asm("mul.rn.f32x2 %0, %1, %2;" : "=l"(D) : "l"(A), "l"(B));
    return *reinterpret_cast<float2*>(&D);
}

// ---------------- fused kernel ----------------
// exp factorization:  exp(leaky(x1+x2)) = max(2^x1 * 2^x2, 2^(.2 x1) * 2^(.2 x2))
// (log2 domain; 2^x > 2^(0.2x) iff x > 0, which is exactly the leaky select)

#define E2_STRIDE 66   // floats per E2p/E2n row
#define R_STRIDE  36   // floats per r row (16B-aligned rows, broadcast-friendly)

struct Smem {
    union {
        struct {                           // live: phases 1..B
            float2 E1pk[WD * VV];          // 16384 B  [w][i] = (2^e1, 2^(.2 e1))
            float  E2p[VV * E2_STRIDE];    //  8448 B  [j][w] = 2^e2
            float  E2n[VV * E2_STRIDE];    //  8448 B  [j][w] = 2^(.2 e2)
        } e;
        struct {                           // live: phase 3
            float  hg[8 * 2 * TT * VV];    // 16384 B  per-warp double-buffered h*g slab
        } p3;
    } u;                                   // 33280 B
    float  adjn[VV * VV];                  //  4096 B  [v][u] (persistent; computed inline)
    float  r[VV * R_STRIDE];               //  4608 B  [j][i] = 1/denominator (also prep scratch)
    float  asum[WD * VV];                  //  8192 B  [w][v] att_sum
    float4 Wt4[OO * 2];                    //   512 B  [o][half]: W[4h..4h+3][o]
    float  wa1[TT], wa2[TT];               //    64 B
};                                          // total 50,752 B -> 4 CTAs/SM, single wave

__global__ __launch_bounds__(256, 4)
void gat_main_kernel(const float* __restrict__ hin,
                     const float* __restrict__ W,
                     const float* __restrict__ a,
                     const float* __restrict__ Bp,
                     float* __restrict__ out) {
    extern __shared__ char smem_raw[];
    Smem& S = *reinterpret_cast<Smem*>(smem_raw);
    const int tid  = threadIdx.x;
    const int lane = tid & 31;
    const int warp = tid >> 5;
    const int n  = blockIdx.x >> 6;
    const int hh = blockIdx.x & 63;
    const float* __restrict__ hbase = hin + (size_t)(n * HH + hh) * (WD * TT * VV);

    // ---- inline prep: adjn (min-max norm + sym-degree norm), wa, Wt4 ----
    {
        float v[4]; float mn = 1e30f, mx = -1e30f;
        #pragma unroll
        for (int k = 0; k < 4; k++) {
            const int e = tid + k * 256;
            float x = Bp[e] + ((e >> 5) == (e & 31) ? 1.0f : 0.0f);
            v[k] = x;
            mn = fminf(mn, x); mx = fmaxf(mx, x);
        }
        #pragma unroll
        for (int o = 16; o; o >>= 1) {
            mn = fminf(mn, __shfl_xor_sync(0xFFFFFFFFu, mn, o));
            mx = fmaxf(mx, __shfl_xor_sync(0xFFFFFFFFu, mx, o));
        }
        if (lane == 0) { S.r[warp] = mn; S.r[8 + warp] = mx; }
        __syncthreads();
        if (tid == 0) {
            float m1 = S.r[0], m2 = S.r[8];
            #pragma unroll
            for (int q = 1; q < 8; q++) {
                m1 = fminf(m1, S.r[q]); m2 = fmaxf(m2, S.r[8 + q]);
            }
            S.r[16] = m1; S.r[17] = m2;
        }
        // stage Wt4 and wa in parallel with the final reduce
        if (tid < 32) {
            const int o = tid >> 1, hf = tid & 1;
            S.Wt4[o * 2 + hf] = make_float4(W[(4 * hf + 0) * OO + o],
                                            W[(4 * hf + 1) * OO + o],
                                            W[(4 * hf + 2) * OO + o],
                                            W[(4 * hf + 3) * OO + o]);
        }
        if (tid >= 32 && tid < 40) {
            const int t = tid - 32;
            float w1 = 0.f, w2 = 0.f;
            #pragma unroll
            for (int o = 0; o < OO; o++) {
                float wv = W[t * OO + o];
                w1 += wv * a[o];
                w2 += wv * a[OO + o];
            }
            S.wa1[t] = w1 * LOG2E;
            S.wa2[t] = w2 * LOG2E;
        }
        __syncthreads();
        const float gmn = S.r[16];
        const float inv = 1.0f / (S.r[17] - gmn);
        #pragma unroll
        for (int k = 0; k < 4; k++) {
            const int e = tid + k * 256;
            S.adjn[e] = (v[k] - gmn) * inv;
        }
        __syncthreads();
        if (tid < 32) {
            float s = 0.f;
            #pragma unroll
            for (int q = 0; q < 8; q++) {
                float4 t4 = *reinterpret_cast<const float4*>(&S.adjn[tid * VV + 4 * q]);
                s += t4.x + t4.y + t4.z + t4.w;
            }
            S.r[32 + tid] = rsqrtf(s);
        }
        __syncthreads();
        #pragma unroll
        for (int k = 0; k < 4; k++) {
            const int e = tid + k * 256;
            S.adjn[e] = S.adjn[e] * S.r[32 + (e >> 5)] * S.r[32 + (e & 31)];
        }
        __syncthreads();
    }

    // ---- phase 1: logits -> exponential tables, streaming h from gmem ----
    {
        float wa1r[TT], wa2r[TT];
        #pragma unroll
        for (int t = 0; t < TT; t++) { wa1r[t] = S.wa1[t]; wa2r[t] = S.wa2[t]; }
        #pragma unroll
        for (int s = 0; s < 2; s++) {
            const int slot = tid + s * 256;
            const int w  = slot >> 3;
            const int vq = slot & 7;
            float4 s1 = make_float4(0.f, 0.f, 0.f, 0.f);
            float4 s2 = make_float4(0.f, 0.f, 0.f, 0.f);
            #pragma unroll
            for (int t = 0; t < TT; t++) {
                float4 h4 = *reinterpret_cast<const float4*>(
                    &hbase[(w * TT + t) * VV + 4 * vq]);   // coalesced LDG.128
                s1.x = fmaf(h4.x, wa1r[t], s1.x);  s2.x = fmaf(h4.x, wa2r[t], s2.x);
                s1.y = fmaf(h4.y, wa1r[t], s1.y);  s2.y = fmaf(h4.y, wa2r[t], s2.y);
                s1.z = fmaf(h4.z, wa1r[t], s1.z);  s2.z = fmaf(h4.z, wa2r[t], s2.z);
                s1.w = fmaf(h4.w, wa1r[t], s1.w);  s2.w = fmaf(h4.w, wa2r[t], s2.w);
            }
            const float l1[4] = {s1.x, s1.y, s1.z, s1.w};
            const float l2[4] = {s2.x, s2.y, s2.z, s2.w};
            #pragma unroll
            for (int c = 0; c < 4; c++) {
                const int v = 4 * vq + c;
                S.u.e.E1pk[w * VV + v] = make_float2(ex2f(l1[c]), ex2f(ALPHA * l1[c]));
                S.u.e.E2p[v * E2_STRIDE + w] = ex2f(l2[c]);
                S.u.e.E2n[v * E2_STRIDE + w] = ex2f(ALPHA * l2[c]);
            }
        }
    }
    __syncthreads();

    // ---- pass A: r[j][i] = 1 / sum_w max(E1p*E2p, E1n*E2n) ----
    {
        const int i0 = warp * 4;
        const int j  = lane;
        float s0 = 0.f, s1 = 0.f, s2 = 0.f, s3 = 0.f;
        #pragma unroll 4
        for (int w = 0; w < WD; w++) {
            const float e2p = S.u.e.E2p[j * E2_STRIDE + w];
            const float e2n = S.u.e.E2n[j * E2_STRIDE + w];
            const float4 A = *reinterpret_cast<const float4*>(&S.u.e.E1pk[w * VV + i0]);
            const float4 B = *reinterpret_cast<const float4*>(&S.u.e.E1pk[w * VV + i0 + 2]);
            s0 += fmaxf(A.x * e2p, A.y * e2n);
            s1 += fmaxf(A.z * e2p, A.w * e2n);
            s2 += fmaxf(B.x * e2p, B.y * e2n);
            s3 += fmaxf(B.z * e2p, B.w * e2n);
        }
        *reinterpret_cast<float4*>(&S.r[j * R_STRIDE + i0]) =
            make_float4(rcpf(s0), rcpf(s1), rcpf(s2), rcpf(s3));
    }
    __syncthreads();

    // ---- pass B: asum[w][i] = sum_j max(E1p*E2p, E1n*E2n) * r[j][i] ----
    {
        const int i0 = warp * 4;
        const int w0 = 2 * lane;
        float2 E1p2[4], E1n2[4];
        #pragma unroll
        for (int k = 0; k < 4; k++) {
            float2 ea = S.u.e.E1pk[w0 * VV + i0 + k];
            float2 eb = S.u.e.E1pk[(w0 + 1) * VV + i0 + k];
            E1p2[k] = make_float2(ea.x, eb.x);
            E1n2[k] = make_float2(ea.y, eb.y);
        }
        float2 acc[4];
        #pragma unroll
        for (int k = 0; k < 4; k++) acc[k] = make_float2(0.f, 0.f);

        #pragma unroll 4
        for (int j = 0; j < VV; j++) {
            const float2 p2 = *reinterpret_cast<const float2*>(&S.u.e.E2p[j * E2_STRIDE + w0]);
            const float2 n2 = *reinterpret_cast<const float2*>(&S.u.e.E2n[j * E2_STRIDE + w0]);
            const float4 rr = *reinterpret_cast<const float4*>(&S.r[j * R_STRIDE + i0]);
            const float rk[4] = {rr.x, rr.y, rr.z, rr.w};
            #pragma unroll
            for (int k = 0; k < 4; k++) {
                float2 pp = fmul2(E1p2[k], p2);
                float2 pn = fmul2(E1n2[k], n2);
                acc[k].x = fmaf(fmaxf(pp.x, pn.x), rk[k], acc[k].x);
                acc[k].y = fmaf(fmaxf(pp.y, pn.y), rk[k], acc[k].y);
            }
        }
        #pragma unroll
        for (int k = 0; k < 4; k++) {
            S.asum[w0 * VV + i0 + k]       = acc[k].x;
            S.asum[(w0 + 1) * VV + i0 + k] = acc[k].y;
        }
    }
    __syncthreads();   // E-tables dead; union region becomes per-warp hg buffers

    // ---- phase 3 (warp-autonomous, double-buffered): warp owns w = warp*8 .. +7 ----
    {
        const int u = lane;
        float* slab = S.u.p3.hg + warp * (2 * TT * VV);   // 2 KB: two 1 KB buffers
        const int sA = lane, sB = lane + 32;              // 64 float4 slots per w
        const int tA = sA >> 3, qA = sA & 7;
        const int tB = sB >> 3, qB = sB & 7;
        const int wbase = warp * 8;

        // prefetch first w
        float4 ha = *reinterpret_cast<const float4*>(&hbase[(wbase * TT + tA) * VV + 4 * qA]);
        float4 hb = *reinterpret_cast<const float4*>(&hbase[(wbase * TT + tB) * VV + 4 * qB]);

        #pragma unroll 1
        for (int c = 0; c < 8; c++) {
            const int w = wbase + c;
            float* hgw = slab + (c & 1) * (TT * VV);      // alternate buffers
            // stage hg = h * asum for this w
            {
                const float4 a1 = *reinterpret_cast<const float4*>(&S.asum[w * VV + 4 * qA]);
                const float4 a2 = *reinterpret_cast<const float4*>(&S.asum[w * VV + 4 * qB]);
                float2 g1 = fmul2(make_float2(ha.x, ha.y), make_float2(a1.x, a1.y));
                float2 g2 = fmul2(make_float2(ha.z, ha.w), make_float2(a1.z, a1.w));
                *reinterpret_cast<float4*>(&hgw[tA * VV + 4 * qA]) =
                    make_float4(g1.x, g1.y, g2.x, g2.y);
                g1 = fmul2(make_float2(hb.x, hb.y), make_float2(a2.x, a2.y));
                g2 = fmul2(make_float2(hb.z, hb.w), make_float2(a2.z, a2.w));
                *reinterpret_cast<float4*>(&hgw[tB * VV + 4 * qB]) =
                    make_float4(g1.x, g1.y, g2.x, g2.y);
            }
            __syncwarp();   // the ONLY barrier per w: orders stage(c) + compute(c-1)
            // prefetch next w (latency hidden behind compute below)
            if (c < 7) {
                ha = *reinterpret_cast<const float4*>(&hbase[((w + 1) * TT + tA) * VV + 4 * qA]);
                hb = *reinterpret_cast<const float4*>(&hbase[((w + 1) * TT + tB) * VV + 4 * qB]);
            }

            // v-contraction: P[t][u] = sum_v hg[t][v] * adjn[v][u]
            float2 acc2[TT];
            #pragma unroll
            for (int t = 0; t < TT; t++) acc2[t] = make_float2(0.f, 0.f);
            #pragma unroll
            for (int vq = 0; vq < 8; vq++) {
                const float2 adjA = make_float2(S.adjn[(4 * vq + 0) * VV + u],
                                                S.adjn[(4 * vq + 1) * VV + u]);
                const float2 adjB = make_float2(S.adjn[(4 * vq + 2) * VV + u],
                                                S.adjn[(4 * vq + 3) * VV + u]);
                #pragma unroll
                for (int t = 0; t < TT; t++) {
                    const float4 h4 = *reinterpret_cast<const float4*>(&hgw[t * VV + 4 * vq]); // broadcast
                    acc2[t] = ffma2(make_float2(h4.x, h4.y), adjA, acc2[t]);
                    acc2[t] = ffma2(make_float2(h4.z, h4.w), adjB, acc2[t]);
                }
            }
            float2 Pt2[4];
            #pragma unroll
            for (int tp = 0; tp < 4; tp++)
                Pt2[tp] = make_float2(acc2[2 * tp].x + acc2[2 * tp].y,
                                      acc2[2 * tp + 1].x + acc2[2 * tp + 1].y);

            // o-loop: out[o][u] = elu( sum_t W[t][o] * P[t][u] ), branch-free ELU
            float* outp = out + ((size_t)((n * WD + w) * HH + hh)) * (OO * VV) + u;
            #pragma unroll
            for (int o = 0; o < OO; o++) {
                const float4 Wa = S.Wt4[2 * o];       // broadcast LDS.128
                const float4 Wb = S.Wt4[2 * o + 1];
                float2 s2 = make_float2(0.f, 0.f);
                s2 = ffma2(Pt2[0], make_float2(Wa.x, Wa.y), s2);
                s2 = ffma2(Pt2[1], make_float2(Wa.z, Wa.w), s2);
                s2 = ffma2(Pt2[2], make_float2(Wb.x, Wb.y), s2);
                s2 = ffma2(Pt2[3], make_float2(Wb.z, Wb.w), s2);
                const float s = s2.x + s2.y;
                // elu(s) = max(s, e^s - 1): equal branches at s=0; e^s-1>s for s<0,
                // and min(s,0) clamps the exp arg so the s>=0 path yields 0.
                outp[o * VV] = fmaxf(s, ex2f(fminf(s, 0.0f) * LOG2E) - 1.0f);
            }
            // no trailing syncwarp: next iteration stages into the OTHER buffer,
            // whose last reader finished before this iteration's syncwarp.
        }
    }
}

// ---------------- launch ----------------
extern "C" void kernel_launch(void* const* d_in, const int* in_sizes, int n_in,
                              void* d_out, int out_size) {
    const float *h = nullptr, *W = nullptr, *a = nullptr, *Bp = nullptr;
    for (int i = 0; i < n_in; i++) {
        switch (in_sizes[i]) {
            case NN * HH * WD * TT * VV: h  = (const float*)d_in[i]; break; // 8388608
            case TT * OO:                W  = (const float*)d_in[i]; break; // 128
            case 2 * OO:                 a  = (const float*)d_in[i]; break; // 32
            case VV * VV:                Bp = (const float*)d_in[i]; break; // 1024
            default: break;
        }
    }
    float* out = (float*)d_out;

    cudaFuncSetAttribute(gat_main_kernel,
                         cudaFuncAttributeMaxDynamicSharedMemorySize,
                         (int)sizeof(Smem));

    gat_main_kernel<<<NN * HH, 256, sizeof(Smem)>>>(h, W, a, Bp, out);
}